// round 11
// baseline (speedup 1.0000x reference)
#include <cuda_runtime.h>
#include <cstdint>
#include <cstddef>

// ---------------------------------------------------------------------------
// Problem constants
// ---------------------------------------------------------------------------
#define BATCH    2
#define SEQ      2048
#define HID      2048
#define HEADS    16
#define HDIM     128
#define KVRANK   256
#define ATTND    2048
#define ROWS     (BATCH * SEQ)          // 4096
#define KVW      (2 * ATTND)            // 4096
#define EPSV     1e-6f
#define NSPLIT   4                      // split-K factor for Wkv_down GEMM

// ---------------------------------------------------------------------------
// Scratch (static device globals; no allocation allowed)
// ---------------------------------------------------------------------------
__device__ float g_q   [(size_t)ROWS * ATTND];            // 32 MB
__device__ float g_lat [(size_t)ROWS * KVRANK];           //  4 MB
__device__ float g_kv  [(size_t)ROWS * KVW];              // 64 MB
__device__ float g_at  [(size_t)ROWS * ATTND];            // 32 MB
__device__ float g_part[(size_t)NSPLIT * ROWS * KVRANK];  // 16 MB

// ---------------------------------------------------------------------------
// TF32 helpers
// ---------------------------------------------------------------------------
__device__ __forceinline__ uint32_t f2tf(float x) {
    uint32_t r;
    asm("cvt.rna.tf32.f32 %0, %1;" : "=r"(r) : "f"(x));
    return r;
}
__device__ __forceinline__ float f2tff(float x) {
    return __uint_as_float(f2tf(x));
}
__device__ __forceinline__ float4 rnd4(float4 v) {
    return make_float4(f2tff(v.x), f2tff(v.y), f2tff(v.z), f2tff(v.w));
}
__device__ __forceinline__ void mma8(float* d, const uint32_t* a,
                                     uint32_t b0, uint32_t b1) {
    asm volatile(
        "mma.sync.aligned.m16n8k8.row.col.f32.tf32.tf32.f32 "
        "{%0,%1,%2,%3}, {%4,%5,%6,%7}, {%8,%9}, {%0,%1,%2,%3};"
        : "+f"(d[0]), "+f"(d[1]), "+f"(d[2]), "+f"(d[3])
        : "r"(a[0]), "r"(a[1]), "r"(a[2]), "r"(a[3]), "r"(b0), "r"(b1));
}

// ---------------------------------------------------------------------------
// TF32 tensor-core GEMM v2: C[M,N] = A[M,K] @ B[K,N], row-major fp32 in/out.
// BM=BN=128, BK=16, 128 threads = 4 warps (2 M x 2 N), warp tile 64x64
// (mma:LDS ratio 1.0 vs 0.67 of the 32x64 version), double-buffered smem,
// RNA tf32 rounding at STS, 2 CTAs/SM.
// lda = row stride of A (allows split-K sub-views); N = row stride of B/C.
// ---------------------------------------------------------------------------
#define TSTR 136

__global__ __launch_bounds__(128, 2) void gemm_tf32(
    const float* __restrict__ A, const float* __restrict__ B,
    float* __restrict__ C, int M, int N, int K, int lda)
{
    __shared__ float As[2][16 * TSTR];
    __shared__ float Bs[2][16 * TSTR];

    const int t     = threadIdx.x;
    const int lane  = t & 31;
    const int wid   = t >> 5;
    const int g     = lane >> 2;
    const int tq    = lane & 3;
    const int warpm = wid & 1;       // 0..1
    const int warpn = wid >> 1;      // 0..1
    const int m0 = blockIdx.y * 128;
    const int n0 = blockIdx.x * 128;

    float4 pa[4], pb[4];

    auto ldA = [&](int k0) {
#pragma unroll
        for (int i = 0; i < 4; i++) {
            int lin = t + i * 128;
            int row = lin >> 2, c4 = lin & 3;
            pa[i] = *(const float4*)&A[(size_t)(m0 + row) * lda + k0 + c4 * 4];
        }
    };
    auto ldB = [&](int k0) {
#pragma unroll
        for (int i = 0; i < 4; i++) {
            int lin = t + i * 128;
            int row = lin >> 5, c4 = lin & 31;
            pb[i] = *(const float4*)&B[(size_t)(k0 + row) * N + n0 + c4 * 4];
        }
    };
    auto stAB = [&](int buf) {
#pragma unroll
        for (int i = 0; i < 4; i++) {
            int lin = t + i * 128;
            int row = lin >> 2, c4 = lin & 3;            // A: transpose store
            float* ap = As[buf];
            ap[(c4 * 4 + 0) * TSTR + row] = f2tff(pa[i].x);
            ap[(c4 * 4 + 1) * TSTR + row] = f2tff(pa[i].y);
            ap[(c4 * 4 + 2) * TSTR + row] = f2tff(pa[i].z);
            ap[(c4 * 4 + 3) * TSTR + row] = f2tff(pa[i].w);
            int brow = lin >> 5, bc4 = lin & 31;         // B: direct store
            *(float4*)&Bs[buf][brow * TSTR + bc4 * 4] = rnd4(pb[i]);
        }
    };

    float acc[4][8][4];
#pragma unroll
    for (int mt = 0; mt < 4; mt++)
#pragma unroll
        for (int nt = 0; nt < 8; nt++)
#pragma unroll
            for (int j = 0; j < 4; j++) acc[mt][nt][j] = 0.f;

    ldA(0); ldB(0); stAB(0);
    __syncthreads();

    int buf = 0;
    for (int k0 = 0; k0 < K; k0 += 16) {
        const bool more = (k0 + 16) < K;
        if (more) { ldA(k0 + 16); ldB(k0 + 16); }

        const uint32_t* ap = (const uint32_t*)As[buf];
        const uint32_t* bp = (const uint32_t*)Bs[buf];
#pragma unroll
        for (int ks = 0; ks < 2; ks++) {
            uint32_t af[4][4];
#pragma unroll
            for (int mt = 0; mt < 4; mt++) {
                int mb = warpm * 64 + mt * 16;
                af[mt][0] = ap[(ks * 8 + tq) * TSTR + mb + g];
                af[mt][1] = ap[(ks * 8 + tq) * TSTR + mb + g + 8];
                af[mt][2] = ap[(ks * 8 + tq + 4) * TSTR + mb + g];
                af[mt][3] = ap[(ks * 8 + tq + 4) * TSTR + mb + g + 8];
            }
#pragma unroll
            for (int nt = 0; nt < 8; nt++) {
                int nb = warpn * 64 + nt * 8;
                uint32_t b0 = bp[(ks * 8 + tq) * TSTR + nb + g];
                uint32_t b1 = bp[(ks * 8 + tq + 4) * TSTR + nb + g];
#pragma unroll
                for (int mt = 0; mt < 4; mt++)
                    mma8(acc[mt][nt], af[mt], b0, b1);
            }
        }
        if (more) {
            stAB(buf ^ 1);
            __syncthreads();
            buf ^= 1;
        }
    }

#pragma unroll
    for (int mt = 0; mt < 4; mt++)
#pragma unroll
        for (int nt = 0; nt < 8; nt++) {
            int row = m0 + warpm * 64 + mt * 16 + g;
            int col = n0 + warpn * 64 + nt * 8 + 2 * tq;
            *(float2*)&C[(size_t)row * N + col] =
                make_float2(acc[mt][nt][0], acc[mt][nt][1]);
            *(float2*)&C[(size_t)(row + 8) * N + col] =
                make_float2(acc[mt][nt][2], acc[mt][nt][3]);
        }
}

// ---------------------------------------------------------------------------
// Fused split-K reduce + RMSNorm: lat[r,:] = rmsnorm(sum_p part[p][r,:]) * w
// ---------------------------------------------------------------------------
__global__ __launch_bounds__(256) void rmsnorm_red(
    const float* __restrict__ part, const float* __restrict__ w,
    float* __restrict__ lat)
{
    const int r = blockIdx.x;
    const int t = threadIdx.x;
    __shared__ float red[256];
    const size_t S = (size_t)ROWS * KVRANK;
    float v = part[(size_t)r * KVRANK + t];
#pragma unroll
    for (int p = 1; p < NSPLIT; p++)
        v += part[p * S + (size_t)r * KVRANK + t];
    red[t] = v * v;
    __syncthreads();
#pragma unroll
    for (int s = 128; s > 0; s >>= 1) {
        if (t < s) red[t] += red[t + s];
        __syncthreads();
    }
    float ms = red[0] * (1.0f / KVRANK);
    lat[(size_t)r * KVRANK + t] = w[t] * v * rsqrtf(ms + EPSV);
}

// ---------------------------------------------------------------------------
// Flash attention (exact config of the 1183.8us best run):
// tf32 mma.sync, causal, BM=128 queries (8 warps x 16 rows), BN=64 keys/iter,
// 256 threads, Q in registers, FA2 register softmax, P C->A via shuffles.
// ---------------------------------------------------------------------------
#define KSTR 132
#define VSTR 136
#define FLASH_SMEM ((64 * KSTR + 64 * VSTR) * 4)

__global__ __launch_bounds__(256, 1) void flash_tc(
    const float* __restrict__ Q, const float* __restrict__ KV,
    float* __restrict__ O)
{
    extern __shared__ float smf[];
    float* Ks = smf;
    float* Vs = smf + 64 * KSTR;

    const int t    = threadIdx.x;
    const int lane = t & 31;
    const int wid  = t >> 5;
    const int g    = lane >> 2;
    const int tq   = lane & 3;
    const int b    = blockIdx.y >> 4;
    const int h    = blockIdx.y & 15;
    const int m0   = blockIdx.x * 128;
    const int wrow = m0 + wid * 16;

    uint32_t qf[16][4];
    const float* Qb = Q + (size_t)(b * SEQ + wrow) * ATTND + h * HDIM;
#pragma unroll
    for (int kt = 0; kt < 16; kt++) {
        qf[kt][0] = f2tf(Qb[(size_t)g * ATTND + kt * 8 + tq]);
        qf[kt][1] = f2tf(Qb[(size_t)(g + 8) * ATTND + kt * 8 + tq]);
        qf[kt][2] = f2tf(Qb[(size_t)g * ATTND + kt * 8 + tq + 4]);
        qf[kt][3] = f2tf(Qb[(size_t)(g + 8) * ATTND + kt * 8 + tq + 4]);
    }

    float oacc[16][4];
#pragma unroll
    for (int nt = 0; nt < 16; nt++)
#pragma unroll
        for (int j = 0; j < 4; j++) oacc[nt][j] = 0.f;

    float mr0 = -1e30f, mr1 = -1e30f, l0 = 0.f, l1 = 0.f;
    const float SC = 0.08838834764831845f;
    const int nkb = 2 * (blockIdx.x + 1);

    for (int kb = 0; kb < nkb; kb++) {
        const float* KVb = KV + (size_t)(b * SEQ + kb * 64) * KVW + h * HDIM;
#pragma unroll
        for (int i = 0; i < 8; i++) {
            int lin = t + i * 256;
            int row = lin >> 5, c4 = lin & 31;
            float4 k4 = *(const float4*)&KVb[(size_t)row * KVW + c4 * 4];
            float4 v4 = *(const float4*)&KVb[(size_t)row * KVW + ATTND + c4 * 4];
            *(float4*)&Ks[row * KSTR + c4 * 4] = rnd4(k4);
            *(float4*)&Vs[row * VSTR + c4 * 4] = rnd4(v4);
        }
        __syncthreads();

        float sacc[8][4];
#pragma unroll
        for (int nt = 0; nt < 8; nt++)
#pragma unroll
            for (int j = 0; j < 4; j++) sacc[nt][j] = 0.f;

        const uint32_t* kp = (const uint32_t*)Ks;
#pragma unroll
        for (int nt = 0; nt < 8; nt++) {
#pragma unroll
            for (int kt = 0; kt < 16; kt++) {
                uint32_t b0 = kp[(nt * 8 + g) * KSTR + kt * 8 + tq];
                uint32_t b1 = kp[(nt * 8 + g) * KSTR + kt * 8 + tq + 4];
                mma8(sacc[nt], qf[kt], b0, b1);
            }
        }

        const int r0 = wrow + g, r1 = r0 + 8;
#pragma unroll
        for (int nt = 0; nt < 8; nt++) {
            int colb = kb * 64 + nt * 8 + 2 * tq;
            sacc[nt][0] = (colb     <= r0) ? sacc[nt][0] * SC : -1e30f;
            sacc[nt][1] = (colb + 1 <= r0) ? sacc[nt][1] * SC : -1e30f;
            sacc[nt][2] = (colb     <= r1) ? sacc[nt][2] * SC : -1e30f;
            sacc[nt][3] = (colb + 1 <= r1) ? sacc[nt][3] * SC : -1e30f;
        }

        float mb0 = -1e30f, mb1 = -1e30f;
#pragma unroll
        for (int nt = 0; nt < 8; nt++) {
            mb0 = fmaxf(mb0, fmaxf(sacc[nt][0], sacc[nt][1]));
            mb1 = fmaxf(mb1, fmaxf(sacc[nt][2], sacc[nt][3]));
        }
        mb0 = fmaxf(mb0, __shfl_xor_sync(0xffffffffu, mb0, 1));
        mb0 = fmaxf(mb0, __shfl_xor_sync(0xffffffffu, mb0, 2));
        mb1 = fmaxf(mb1, __shfl_xor_sync(0xffffffffu, mb1, 1));
        mb1 = fmaxf(mb1, __shfl_xor_sync(0xffffffffu, mb1, 2));

        float mn0 = fmaxf(mr0, mb0), mn1 = fmaxf(mr1, mb1);
        float al0 = __expf(mr0 - mn0), al1 = __expf(mr1 - mn1);
        mr0 = mn0; mr1 = mn1;

        float ps0 = 0.f, ps1 = 0.f;
#pragma unroll
        for (int nt = 0; nt < 8; nt++) {
            sacc[nt][0] = __expf(sacc[nt][0] - mn0);
            sacc[nt][1] = __expf(sacc[nt][1] - mn0);
            sacc[nt][2] = __expf(sacc[nt][2] - mn1);
            sacc[nt][3] = __expf(sacc[nt][3] - mn1);
            ps0 += sacc[nt][0] + sacc[nt][1];
            ps1 += sacc[nt][2] + sacc[nt][3];
        }
        ps0 += __shfl_xor_sync(0xffffffffu, ps0, 1);
        ps0 += __shfl_xor_sync(0xffffffffu, ps0, 2);
        ps1 += __shfl_xor_sync(0xffffffffu, ps1, 1);
        ps1 += __shfl_xor_sync(0xffffffffu, ps1, 2);
        l0 = l0 * al0 + ps0;
        l1 = l1 * al1 + ps1;

#pragma unroll
        for (int nt = 0; nt < 16; nt++) {
            oacc[nt][0] *= al0; oacc[nt][1] *= al0;
            oacc[nt][2] *= al1; oacc[nt][3] *= al1;
        }

        const uint32_t* vp = (const uint32_t*)Vs;
#pragma unroll
        for (int kt2 = 0; kt2 < 8; kt2++) {
            uint32_t pc0 = f2tf(sacc[kt2][0]), pc1 = f2tf(sacc[kt2][1]);
            uint32_t pc2 = f2tf(sacc[kt2][2]), pc3 = f2tf(sacc[kt2][3]);
            int base = lane & ~3;
            int s0 = base + (tq >> 1), s1 = s0 + 2;
            uint32_t x0 = __shfl_sync(0xffffffffu, pc0, s0);
            uint32_t x1 = __shfl_sync(0xffffffffu, pc1, s0);
            uint32_t x2 = __shfl_sync(0xffffffffu, pc2, s0);
            uint32_t x3 = __shfl_sync(0xffffffffu, pc3, s0);
            uint32_t y0 = __shfl_sync(0xffffffffu, pc0, s1);
            uint32_t y1 = __shfl_sync(0xffffffffu, pc1, s1);
            uint32_t y2 = __shfl_sync(0xffffffffu, pc2, s1);
            uint32_t y3 = __shfl_sync(0xffffffffu, pc3, s1);
            uint32_t af[4];
            af[0] = (tq & 1) ? x1 : x0;
            af[1] = (tq & 1) ? x3 : x2;
            af[2] = (tq & 1) ? y1 : y0;
            af[3] = (tq & 1) ? y3 : y2;
#pragma unroll
            for (int nt2 = 0; nt2 < 16; nt2++) {
                uint32_t b0 = vp[(kt2 * 8 + tq) * VSTR + nt2 * 8 + g];
                uint32_t b1 = vp[(kt2 * 8 + tq + 4) * VSTR + nt2 * 8 + g];
                mma8(oacc[nt2], af, b0, b1);
            }
        }
        __syncthreads();
    }

    const float inv0 = 1.f / l0, inv1 = 1.f / l1;
#pragma unroll
    for (int nt2 = 0; nt2 < 16; nt2++) {
        size_t o0 = (size_t)(b * SEQ + wrow + g) * ATTND + h * HDIM + nt2 * 8 + 2 * tq;
        *(float2*)&O[o0] = make_float2(oacc[nt2][0] * inv0, oacc[nt2][1] * inv0);
        *(float2*)&O[o0 + (size_t)8 * ATTND] =
            make_float2(oacc[nt2][2] * inv1, oacc[nt2][3] * inv1);
    }
}

// ---------------------------------------------------------------------------
// Launch. Wkv_down is split-K x4 (64 CTAs each -> full-chip waves), reduced
// inside a fused reduce+RMSNorm. Launch order puts the Wq GEMM 4th so the
// profiler (which captures the 4th kernel launch) shows the big GEMM.
// ---------------------------------------------------------------------------
extern "C" void kernel_launch(void* const* d_in, const int* in_sizes, int n_in,
                              void* d_out, int out_size)
{
    const float* x     = (const float*)d_in[0];
    const float* Wq    = (const float*)d_in[1];
    const float* Wkd   = (const float*)d_in[2];
    const float* wnorm = (const float*)d_in[3];
    const float* Wku   = (const float*)d_in[4];
    const float* Wo    = (const float*)d_in[5];
    float* out = (float*)d_out;

    float *q, *lat, *kv, *at, *part;
    cudaGetSymbolAddress((void**)&q,    g_q);
    cudaGetSymbolAddress((void**)&lat,  g_lat);
    cudaGetSymbolAddress((void**)&kv,   g_kv);
    cudaGetSymbolAddress((void**)&at,   g_at);
    cudaGetSymbolAddress((void**)&part, g_part);

    cudaFuncSetAttribute(flash_tc,
                         cudaFuncAttributeMaxDynamicSharedMemorySize,
                         FLASH_SMEM);

    const int KC = HID / NSPLIT;   // 512
    const size_t S = (size_t)ROWS * KVRANK;

    // 1-3: Wkv_down split-K partials 0..2   [4096,512] x [512,256] each
    gemm_tf32<<<dim3(KVRANK / 128, ROWS / 128), 128>>>(
        x + 0 * KC, Wkd + (size_t)(0 * KC) * KVRANK, part + 0 * S,
        ROWS, KVRANK, KC, HID);
    gemm_tf32<<<dim3(KVRANK / 128, ROWS / 128), 128>>>(
        x + 1 * KC, Wkd + (size_t)(1 * KC) * KVRANK, part + 1 * S,
        ROWS, KVRANK, KC, HID);
    gemm_tf32<<<dim3(KVRANK / 128, ROWS / 128), 128>>>(
        x + 2 * KC, Wkd + (size_t)(2 * KC) * KVRANK, part + 2 * S,
        ROWS, KVRANK, KC, HID);
    // 4 (profiled): q = x @ Wq        [4096,2048] x [2048,2048]
    gemm_tf32<<<dim3(ATTND / 128, ROWS / 128), 128>>>(x, Wq, q, ROWS, ATTND, HID, HID);
    // 5: Wkv_down split-K partial 3
    gemm_tf32<<<dim3(KVRANK / 128, ROWS / 128), 128>>>(
        x + 3 * KC, Wkd + (size_t)(3 * KC) * KVRANK, part + 3 * S,
        ROWS, KVRANK, KC, HID);
    // 6: latent = rmsnorm(sum of partials)
    rmsnorm_red<<<ROWS, 256>>>(part, wnorm, lat);
    // 7: kv = latent @ Wkv_up         [4096,256] x [256,4096]
    gemm_tf32<<<dim3(KVW / 128, ROWS / 128), 128>>>(lat, Wku, kv, ROWS, KVW, KVRANK, KVRANK);
    // 8: attention
    flash_tc<<<dim3(SEQ / 128, BATCH * HEADS), 256, FLASH_SMEM>>>(q, kv, at);
    // 9: out = attn @ Wo              [4096,2048] x [2048,2048]
    gemm_tf32<<<dim3(HID / 128, ROWS / 128), 128>>>(at, Wo, out, ROWS, HID, ATTND, ATTND);
}

// round 14
// speedup vs baseline: 2.1290x; 2.1290x over previous
#include <cuda_runtime.h>
#include <cuda_fp16.h>
#include <cstdint>
#include <cstddef>

// ---------------------------------------------------------------------------
// Problem constants
// ---------------------------------------------------------------------------
#define BATCH    2
#define SEQ      2048
#define HID      2048
#define HEADS    16
#define HDIM     128
#define KVRANK   256
#define ATTND    2048
#define ROWS     (BATCH * SEQ)          // 4096
#define KVW      (2 * ATTND)            // 4096
#define EPSV     1e-6f
#define NSPLIT   4

// ---------------------------------------------------------------------------
// Scratch (static device globals; no allocation allowed)
// ---------------------------------------------------------------------------
__device__ __half g_qh [(size_t)ROWS * ATTND];            // 16 MB
__device__ float  g_lat[(size_t)ROWS * KVRANK];           //  4 MB
__device__ __half g_kvh[(size_t)ROWS * KVW];              // 32 MB
__device__ __half g_ath[(size_t)ROWS * ATTND];            // 16 MB
__device__ float  g_part[(size_t)NSPLIT * ROWS * KVRANK]; // 16 MB

// ---------------------------------------------------------------------------
// Helpers
// ---------------------------------------------------------------------------
__device__ __forceinline__ uint32_t pack2(float lo, float hi) {
    __half2 h = __floats2half2_rn(lo, hi);
    return *reinterpret_cast<uint32_t*>(&h);
}
__device__ __forceinline__ void mma16(float* d, const uint32_t* a,
                                      uint32_t b0, uint32_t b1) {
    asm volatile(
        "mma.sync.aligned.m16n8k16.row.col.f32.f16.f16.f32 "
        "{%0,%1,%2,%3}, {%4,%5,%6,%7}, {%8,%9}, {%0,%1,%2,%3};"
        : "+f"(d[0]), "+f"(d[1]), "+f"(d[2]), "+f"(d[3])
        : "r"(a[0]), "r"(a[1]), "r"(a[2]), "r"(a[3]), "r"(b0), "r"(b1));
}
#define LDSM4(r0, r1, r2, r3, addr)                                         \
    asm volatile("ldmatrix.sync.aligned.m8n8.x4.shared.b16 "                \
                 "{%0,%1,%2,%3}, [%4];"                                     \
                 : "=r"(r0), "=r"(r1), "=r"(r2), "=r"(r3) : "r"(addr))
#define LDSM4T(r0, r1, r2, r3, addr)                                        \
    asm volatile("ldmatrix.sync.aligned.m8n8.x4.trans.shared.b16 "          \
                 "{%0,%1,%2,%3}, [%4];"                                     \
                 : "=r"(r0), "=r"(r1), "=r"(r2), "=r"(r3) : "r"(addr))
__device__ __forceinline__ uint32_t s2u(const void* p) {
    uint32_t a;
    asm("{ .reg .u64 t; cvta.to.shared.u64 t, %1; cvt.u32.u64 %0, t; }"
        : "=r"(a) : "l"(p));
    return a;
}

// ---------------------------------------------------------------------------
// fp16 tensor-core GEMM: C = A @ B, A row-major [M,K] (fp32 or fp16),
// B row-major fp32 [K,N], C fp32 or fp16.
// BM=BN=128, BK=16, 256 threads = 8 warps (4 M x 2 N), warp tile 32x64,
// m16n8k16 HMMA, ldmatrix fragment loads, double-buffered smem (stride 12
// words/row, conflict-free LDSM phases), 2 CTAs/SM.
// lda = row stride of A. Requires M%128==0, N%128==0, K%16==0.
// ---------------------------------------------------------------------------
template <bool HA, bool HC>
__global__ __launch_bounds__(256, 2) void gemm_h(
    const void* __restrict__ Ap, const float* __restrict__ B,
    void* __restrict__ Cp, int M, int N, int K, int lda)
{
    __shared__ uint32_t Ash[2][128 * 12];   // [m][8 words of half2], stride 12
    __shared__ uint32_t Bsh[2][128 * 12];   // [n][8 words of half2], stride 12

    const int t     = threadIdx.x;
    const int lane  = t & 31;
    const int wid   = t >> 5;
    const int g     = lane >> 2;
    const int tq    = lane & 3;
    const int warpm = wid & 3;
    const int warpn = wid >> 2;
    const int m0 = blockIdx.y * 128;
    const int n0 = blockIdx.x * 128;

    const int am = t >> 1;            // A row handled by this thread
    const int akq = t & 1;            // which 8-half quad
    const int bn = t & 127;           // B column handled
    const int bkg = t >> 7;           // which k-octet

    // prefetch registers
    float4 pa0, pa1; uint4 pah; float pb[8];

    auto ldA = [&](int c) {
        if constexpr (HA) {
            const __half* Ah = (const __half*)Ap;
            pah = *(const uint4*)&Ah[(size_t)(m0 + am) * lda + c * 16 + akq * 8];
        } else {
            const float* Af = (const float*)Ap;
            const float* p = &Af[(size_t)(m0 + am) * lda + c * 16 + akq * 8];
            pa0 = *(const float4*)p;
            pa1 = *(const float4*)(p + 4);
        }
    };
    auto ldB = [&](int c) {
        const float* p = &B[(size_t)(c * 16 + bkg * 8) * N + n0 + bn];
#pragma unroll
        for (int j = 0; j < 8; j++) pb[j] = p[(size_t)j * N];
    };
    auto stAB = [&](int buf) {
        uint4 wa;
        if constexpr (HA) {
            wa = pah;
        } else {
            wa.x = pack2(pa0.x, pa0.y); wa.y = pack2(pa0.z, pa0.w);
            wa.z = pack2(pa1.x, pa1.y); wa.w = pack2(pa1.z, pa1.w);
        }
        *(uint4*)&Ash[buf][am * 12 + akq * 4] = wa;
        uint4 wb;
        wb.x = pack2(pb[0], pb[1]); wb.y = pack2(pb[2], pb[3]);
        wb.z = pack2(pb[4], pb[5]); wb.w = pack2(pb[6], pb[7]);
        *(uint4*)&Bsh[buf][bn * 12 + bkg * 4] = wb;
    };

    // ldmatrix lane addresses (bytes, shared space)
    const int arow = warpm * 32 + (lane & 7) + 8 * ((lane >> 3) & 1);
    const int aw   = 4 * (lane >> 4);
    const int brow = warpn * 64 + (lane & 7) + 8 * ((lane >> 4) & 1);
    const int bw   = 4 * ((lane >> 3) & 1);
    uint32_t aAddr[2], bAddr[2];
#pragma unroll
    for (int s = 0; s < 2; s++) {
        aAddr[s] = s2u(&Ash[s][0]) + (uint32_t)(arow * 12 + aw) * 4;
        bAddr[s] = s2u(&Bsh[s][0]) + (uint32_t)(brow * 12 + bw) * 4;
    }

    float acc[2][8][4];
#pragma unroll
    for (int mt = 0; mt < 2; mt++)
#pragma unroll
        for (int nt = 0; nt < 8; nt++)
#pragma unroll
            for (int j = 0; j < 4; j++) acc[mt][nt][j] = 0.f;

    const int nc = K / 16;
    ldA(0); ldB(0); stAB(0);
    __syncthreads();

    int buf = 0;
    for (int c = 0; c < nc; c++) {
        const bool more = (c + 1) < nc;
        if (more) { ldA(c + 1); ldB(c + 1); }

        uint32_t af[2][4];
        LDSM4(af[0][0], af[0][1], af[0][2], af[0][3], aAddr[buf]);
        LDSM4(af[1][0], af[1][1], af[1][2], af[1][3], aAddr[buf] + 768);
#pragma unroll
        for (int u = 0; u < 4; u++) {
            uint32_t b0, b1, b2, b3;
            LDSM4(b0, b1, b2, b3, bAddr[buf] + u * 768);
            mma16(acc[0][2 * u],     af[0], b0, b1);
            mma16(acc[1][2 * u],     af[1], b0, b1);
            mma16(acc[0][2 * u + 1], af[0], b2, b3);
            mma16(acc[1][2 * u + 1], af[1], b2, b3);
        }
        if (more) {
            stAB(buf ^ 1);
            __syncthreads();
            buf ^= 1;
        }
    }

#pragma unroll
    for (int mt = 0; mt < 2; mt++)
#pragma unroll
        for (int nt = 0; nt < 8; nt++) {
            int row = m0 + warpm * 32 + mt * 16 + g;
            int col = n0 + warpn * 64 + nt * 8 + 2 * tq;
            if constexpr (HC) {
                uint32_t* Ch = (uint32_t*)Cp;
                Ch[((size_t)row * N + col) >> 1] =
                    pack2(acc[mt][nt][0], acc[mt][nt][1]);
                Ch[((size_t)(row + 8) * N + col) >> 1] =
                    pack2(acc[mt][nt][2], acc[mt][nt][3]);
            } else {
                float* Cf = (float*)Cp;
                *(float2*)&Cf[(size_t)row * N + col] =
                    make_float2(acc[mt][nt][0], acc[mt][nt][1]);
                *(float2*)&Cf[(size_t)(row + 8) * N + col] =
                    make_float2(acc[mt][nt][2], acc[mt][nt][3]);
            }
        }
}

// ---------------------------------------------------------------------------
// Fused split-K reduce + RMSNorm: lat[r,:] = rmsnorm(sum_p part[p][r,:]) * w
// ---------------------------------------------------------------------------
__global__ __launch_bounds__(256) void rmsnorm_red(
    const float* __restrict__ part, const float* __restrict__ w,
    float* __restrict__ lat)
{
    const int r = blockIdx.x;
    const int t = threadIdx.x;
    __shared__ float red[256];
    const size_t S = (size_t)ROWS * KVRANK;
    float v = part[(size_t)r * KVRANK + t];
#pragma unroll
    for (int p = 1; p < NSPLIT; p++)
        v += part[p * S + (size_t)r * KVRANK + t];
    red[t] = v * v;
    __syncthreads();
#pragma unroll
    for (int s = 128; s > 0; s >>= 1) {
        if (t < s) red[t] += red[t + s];
        __syncthreads();
    }
    float ms = red[0] * (1.0f / KVRANK);
    lat[(size_t)r * KVRANK + t] = w[t] * v * rsqrtf(ms + EPSV);
}

// ---------------------------------------------------------------------------
// Flash attention fp16: m16n8k16 HMMA, causal, BM=128 (8 warps x 16 rows),
// BN=64 keys/iter, D=128, 256 threads. Q/KV fp16 in gmem; K frags via
// ldmatrix.x4, V frags via ldmatrix.x4.trans; P C-layout == A-layout
// (no shuffles). Smem rows stride 68 words (conflict-free LDSM phases).
// ---------------------------------------------------------------------------
__global__ __launch_bounds__(256, 1) void flash_h(
    const __half* __restrict__ Q, const __half* __restrict__ KV,
    __half* __restrict__ O)
{
    __shared__ uint32_t Ks[64 * 68];
    __shared__ uint32_t Vs[64 * 68];

    const int t    = threadIdx.x;
    const int lane = t & 31;
    const int wid  = t >> 5;
    const int g    = lane >> 2;
    const int tq   = lane & 3;
    const int b    = blockIdx.y >> 4;
    const int h    = blockIdx.y & 15;
    const int m0   = blockIdx.x * 128;
    const int wrow = m0 + wid * 16;

    const uint32_t ksb = s2u(Ks), vsb = s2u(Vs);
    const uint32_t klane = (uint32_t)((lane & 7) * 68 + 4 * (lane >> 3)) * 4;
    const uint32_t vlane =
        (uint32_t)(((lane & 7) + 8 * ((lane >> 3) & 1)) * 68 + 4 * (lane >> 4)) * 4;

    // Q fragments: 8 k16-tiles x 4 regs (half2 words straight from gmem)
    uint32_t qf[8][4];
    {
        const uint32_t* Qu = (const uint32_t*)Q;
        const size_t base = (size_t)(b * SEQ + wrow) * ATTND + h * HDIM;
#pragma unroll
        for (int kt = 0; kt < 8; kt++) {
            qf[kt][0] = Qu[(base + (size_t)g * ATTND + kt * 16 + 2 * tq) >> 1];
            qf[kt][1] = Qu[(base + (size_t)(g + 8) * ATTND + kt * 16 + 2 * tq) >> 1];
            qf[kt][2] = Qu[(base + (size_t)g * ATTND + kt * 16 + 8 + 2 * tq) >> 1];
            qf[kt][3] = Qu[(base + (size_t)(g + 8) * ATTND + kt * 16 + 8 + 2 * tq) >> 1];
        }
    }

    float oacc[16][4];
#pragma unroll
    for (int nt = 0; nt < 16; nt++)
#pragma unroll
        for (int j = 0; j < 4; j++) oacc[nt][j] = 0.f;

    float mr0 = -1e30f, mr1 = -1e30f, l0 = 0.f, l1 = 0.f;
    const float SC = 0.08838834764831845f;   // 1/sqrt(128)
    const int nkb = 2 * (blockIdx.x + 1);

    for (int kb = 0; kb < nkb; kb++) {
        // --- load K,V tile (fp16, straight copies) ---
#pragma unroll
        for (int i = 0; i < 4; i++) {
            int lin = t + i * 256;
            int row = lin >> 4, q4 = lin & 15;
            const size_t ofs =
                (size_t)(b * SEQ + kb * 64 + row) * KVW + h * HDIM + q4 * 8;
            *(uint4*)&Ks[row * 68 + q4 * 4] = *(const uint4*)&KV[ofs];
            *(uint4*)&Vs[row * 68 + q4 * 4] = *(const uint4*)&KV[ofs + ATTND];
        }
        __syncthreads();

        // --- S = Q K^T ---
        float sacc[8][4];
#pragma unroll
        for (int nt = 0; nt < 8; nt++) {
#pragma unroll
            for (int j = 0; j < 4; j++) sacc[nt][j] = 0.f;
#pragma unroll
            for (int ktp = 0; ktp < 4; ktp++) {
                uint32_t b0, b1, b2, b3;
                LDSM4(b0, b1, b2, b3,
                      ksb + klane + (uint32_t)(nt * 2176 + ktp * 64));
                mma16(sacc[nt], qf[2 * ktp],     b0, b1);
                mma16(sacc[nt], qf[2 * ktp + 1], b2, b3);
            }
        }

        // --- scale + causal mask ---
        const int r0 = wrow + g, r1 = r0 + 8;
#pragma unroll
        for (int nt = 0; nt < 8; nt++) {
            int colb = kb * 64 + nt * 8 + 2 * tq;
            sacc[nt][0] = (colb     <= r0) ? sacc[nt][0] * SC : -1e30f;
            sacc[nt][1] = (colb + 1 <= r0) ? sacc[nt][1] * SC : -1e30f;
            sacc[nt][2] = (colb     <= r1) ? sacc[nt][2] * SC : -1e30f;
            sacc[nt][3] = (colb + 1 <= r1) ? sacc[nt][3] * SC : -1e30f;
        }

        // --- online softmax ---
        float mb0 = -1e30f, mb1 = -1e30f;
#pragma unroll
        for (int nt = 0; nt < 8; nt++) {
            mb0 = fmaxf(mb0, fmaxf(sacc[nt][0], sacc[nt][1]));
            mb1 = fmaxf(mb1, fmaxf(sacc[nt][2], sacc[nt][3]));
        }
        mb0 = fmaxf(mb0, __shfl_xor_sync(0xffffffffu, mb0, 1));
        mb0 = fmaxf(mb0, __shfl_xor_sync(0xffffffffu, mb0, 2));
        mb1 = fmaxf(mb1, __shfl_xor_sync(0xffffffffu, mb1, 1));
        mb1 = fmaxf(mb1, __shfl_xor_sync(0xffffffffu, mb1, 2));

        float mn0 = fmaxf(mr0, mb0), mn1 = fmaxf(mr1, mb1);
        float al0 = __expf(mr0 - mn0), al1 = __expf(mr1 - mn1);
        mr0 = mn0; mr1 = mn1;

        float ps0 = 0.f, ps1 = 0.f;
#pragma unroll
        for (int nt = 0; nt < 8; nt++) {
            sacc[nt][0] = __expf(sacc[nt][0] - mn0);
            sacc[nt][1] = __expf(sacc[nt][1] - mn0);
            sacc[nt][2] = __expf(sacc[nt][2] - mn1);
            sacc[nt][3] = __expf(sacc[nt][3] - mn1);
            ps0 += sacc[nt][0] + sacc[nt][1];
            ps1 += sacc[nt][2] + sacc[nt][3];
        }
        ps0 += __shfl_xor_sync(0xffffffffu, ps0, 1);
        ps0 += __shfl_xor_sync(0xffffffffu, ps0, 2);
        ps1 += __shfl_xor_sync(0xffffffffu, ps1, 1);
        ps1 += __shfl_xor_sync(0xffffffffu, ps1, 2);
        l0 = l0 * al0 + ps0;
        l1 = l1 * al1 + ps1;

#pragma unroll
        for (int nt = 0; nt < 16; nt++) {
            oacc[nt][0] *= al0; oacc[nt][1] *= al0;
            oacc[nt][2] *= al1; oacc[nt][3] *= al1;
        }

        // --- O += P V (P: C-layout == A-layout, register-local pack) ---
#pragma unroll
        for (int kt2 = 0; kt2 < 4; kt2++) {
            uint32_t pf[4];
            pf[0] = pack2(sacc[2 * kt2][0],     sacc[2 * kt2][1]);
            pf[1] = pack2(sacc[2 * kt2][2],     sacc[2 * kt2][3]);
            pf[2] = pack2(sacc[2 * kt2 + 1][0], sacc[2 * kt2 + 1][1]);
            pf[3] = pack2(sacc[2 * kt2 + 1][2], sacc[2 * kt2 + 1][3]);
#pragma unroll
            for (int ntp = 0; ntp < 8; ntp++) {
                uint32_t v0, v1, v2, v3;
                LDSM4T(v0, v1, v2, v3,
                       vsb + vlane + (uint32_t)(kt2 * 4352 + ntp * 32));
                mma16(oacc[2 * ntp],     pf, v0, v1);
                mma16(oacc[2 * ntp + 1], pf, v2, v3);
            }
        }
        __syncthreads();
    }

    // --- epilogue: O = acc / l (fp16 out) ---
    const float inv0 = 1.f / l0, inv1 = 1.f / l1;
    uint32_t* Ou = (uint32_t*)O;
#pragma unroll
    for (int nt2 = 0; nt2 < 16; nt2++) {
        size_t o0 = (size_t)(b * SEQ + wrow + g) * ATTND + h * HDIM
                  + nt2 * 8 + 2 * tq;
        Ou[o0 >> 1] = pack2(oacc[nt2][0] * inv0, oacc[nt2][1] * inv0);
        Ou[(o0 + (size_t)8 * ATTND) >> 1] =
            pack2(oacc[nt2][2] * inv1, oacc[nt2][3] * inv1);
    }
}

// ---------------------------------------------------------------------------
// Launch. Order keeps the big Wq GEMM as the 4th launch (the one ncu
// captures). Wkv_down is split-K x4 with fused reduce+RMSNorm.
// ---------------------------------------------------------------------------
extern "C" void kernel_launch(void* const* d_in, const int* in_sizes, int n_in,
                              void* d_out, int out_size)
{
    const float* x     = (const float*)d_in[0];
    const float* Wq    = (const float*)d_in[1];
    const float* Wkd   = (const float*)d_in[2];
    const float* wnorm = (const float*)d_in[3];
    const float* Wku   = (const float*)d_in[4];
    const float* Wo    = (const float*)d_in[5];
    float* out = (float*)d_out;

    __half *qh, *kvh, *ath;
    float *lat, *part;
    cudaGetSymbolAddress((void**)&qh,   g_qh);
    cudaGetSymbolAddress((void**)&lat,  g_lat);
    cudaGetSymbolAddress((void**)&kvh,  g_kvh);
    cudaGetSymbolAddress((void**)&ath,  g_ath);
    cudaGetSymbolAddress((void**)&part, g_part);

    const int KC = HID / NSPLIT;   // 512
    const size_t S = (size_t)ROWS * KVRANK;

    // 1-3: Wkv_down split-K partials 0..2  (fp32 A, fp32 C)
    gemm_h<false, false><<<dim3(KVRANK / 128, ROWS / 128), 256>>>(
        x + 0 * KC, Wkd + (size_t)(0 * KC) * KVRANK, part + 0 * S,
        ROWS, KVRANK, KC, HID);
    gemm_h<false, false><<<dim3(KVRANK / 128, ROWS / 128), 256>>>(
        x + 1 * KC, Wkd + (size_t)(1 * KC) * KVRANK, part + 1 * S,
        ROWS, KVRANK, KC, HID);
    gemm_h<false, false><<<dim3(KVRANK / 128, ROWS / 128), 256>>>(
        x + 2 * KC, Wkd + (size_t)(2 * KC) * KVRANK, part + 2 * S,
        ROWS, KVRANK, KC, HID);
    // 4 (profiled): q = x @ Wq  -> fp16
    gemm_h<false, true><<<dim3(ATTND / 128, ROWS / 128), 256>>>(
        x, Wq, qh, ROWS, ATTND, HID, HID);
    // 5: Wkv_down split-K partial 3
    gemm_h<false, false><<<dim3(KVRANK / 128, ROWS / 128), 256>>>(
        x + 3 * KC, Wkd + (size_t)(3 * KC) * KVRANK, part + 3 * S,
        ROWS, KVRANK, KC, HID);
    // 6: latent = rmsnorm(sum of partials)  (fp32)
    rmsnorm_red<<<ROWS, 256>>>(part, wnorm, lat);
    // 7: kv = latent @ Wkv_up -> fp16
    gemm_h<false, true><<<dim3(KVW / 128, ROWS / 128), 256>>>(
        lat, Wku, kvh, ROWS, KVW, KVRANK, KVRANK);
    // 8: attention (fp16 in/out)
    flash_h<<<dim3(SEQ / 128, BATCH * HEADS), 256>>>(qh, kvh, ath);
    // 9: out = attn @ Wo  (fp16 A, fp32 C)
    gemm_h<true, false><<<dim3(HID / 128, ROWS / 128), 256>>>(
        ath, Wo, out, ROWS, HID, ATTND, ATTND);
}